// round 12
// baseline (speedup 1.0000x reference)
#include <cuda_runtime.h>
#include <cuda_fp16.h>
#include <math.h>
#include <stdint.h>

// Problem constants
#define S_   1024
#define B_   8
#define D_   512
#define H_   8
#define HD_  64
#define FF_  2048
#define N_   (S_ * B_)      // 8192 tokens
#define NH_  (B_ * H_)      // 64 (batch*heads)
#define DD_  (D_ * D_)

// ===========================================================================
// PTX helpers — baseline-PTX only (compute_103 virtual arch: NO tcgen05)
// ===========================================================================
__device__ __forceinline__ uint32_t smem_u32(const void* p) {
    uint32_t a;
    asm("{ .reg .u64 t; cvta.to.shared.u64 t, %1; cvt.u32.u64 %0, t; }" : "=r"(a) : "l"(p));
    return a;
}

__device__ __forceinline__ void cpasync16(uint32_t s, const void* g) {
    asm volatile("cp.async.cg.shared.global [%0], [%1], 16;" :: "r"(s), "l"(g));
}
#define CP_COMMIT()  asm volatile("cp.async.commit_group;" ::: "memory")
#define CP_WAIT0()   asm volatile("cp.async.wait_group 0;" ::: "memory")
#define CP_WAIT1()   asm volatile("cp.async.wait_group 1;" ::: "memory")
#define CP_WAIT2()   asm volatile("cp.async.wait_group 2;" ::: "memory")

__device__ __forceinline__ void ldsm4(uint32_t r[4], uint32_t addr) {
    asm volatile("ldmatrix.sync.aligned.m8n8.x4.shared.b16 {%0,%1,%2,%3}, [%4];"
        : "=r"(r[0]), "=r"(r[1]), "=r"(r[2]), "=r"(r[3]) : "r"(addr));
}

// Transposing ldmatrix: for row-major [K,N] tiles used as B operands.
__device__ __forceinline__ void ldsm4t(uint32_t r[4], uint32_t addr) {
    asm volatile("ldmatrix.sync.aligned.m8n8.x4.trans.shared.b16 {%0,%1,%2,%3}, [%4];"
        : "=r"(r[0]), "=r"(r[1]), "=r"(r[2]), "=r"(r[3]) : "r"(addr));
}

// fp16 MMA, fp32 accumulate
__device__ __forceinline__ void mma16816(float acc[4], const uint32_t a[4], const uint32_t b[2]) {
    asm volatile(
        "mma.sync.aligned.m16n8k16.row.col.f32.f16.f16.f32 "
        "{%0,%1,%2,%3}, {%4,%5,%6,%7}, {%8,%9}, {%0,%1,%2,%3};"
        : "+f"(acc[0]), "+f"(acc[1]), "+f"(acc[2]), "+f"(acc[3])
        : "r"(a[0]), "r"(a[1]), "r"(a[2]), "r"(a[3]), "r"(b[0]), "r"(b[1]));
}

// ===========================================================================
// Scratch (static device memory)
// ===========================================================================
__device__ __half g_wih[4*DD_], g_wdh[4*DD_];
__device__ __half g_w1ih[FF_*D_], g_w2ih[D_*FF_];
__device__ __half g_w1dh[FF_*D_], g_w2dh[D_*FF_];
__device__ __half g_qkinh[N_*D_];
__device__ __half g_srch[N_*D_], g_srcdh[N_*D_];
__device__ __half g_qh[N_*D_],  g_qdh[N_*D_];
__device__ __half g_kh[N_*D_],  g_kdh[N_*D_];
__device__ __half g_vh[N_*D_],  g_vdh[N_*D_];
__device__ __half g_oih[N_*D_], g_odh[N_*D_];
__device__ float  g_t2[2*N_*D_];
__device__ float  g_x2[2*N_*D_];
__device__ __half g_x2h[2*N_*D_];
__device__ __half g_ff2[2*N_*FF_];

// ===========================================================================
// Z-batched mma.sync GEMM (R10 known-good config):
//   C_z[M,N] = A_z[M,K] * B_z[N,K]^T + bias_z
// BM_ in {128, 64}; BN=128; BK=32. 256 threads = 8 warps (2x4), 64x32 warp tile.
// 3-stage cp.async pipeline; 80B padded smem rows (conflict-free ldmatrix).
// ===========================================================================
template<int NZ>
struct GP {
    const __half* A[NZ];
    const __half* B[NZ];
    const float*  bias[NZ];
    float*        Cf[NZ];
    __half*       Ch[NZ];
};

template<int NZ, int BM_, bool RELU, bool HALF_OUT>
__global__ __launch_bounds__(256) void mma_gemm(
    GP<NZ> p, int K, int lda, int ldb, int ldc)
{
    constexpr int BN = 128;
    constexpr int WM = BM_ / 2;
    constexpr int MT = WM / 16;
    constexpr int RS = 80;
    constexpr int SA = BM_ * RS;
    constexpr int STAGE = SA + BN * RS;

    extern __shared__ char sm[];
    const uint32_t smb = smem_u32(sm);

    const int t = threadIdx.x;
    const int lane = t & 31, wid = t >> 5;
    const int wm = wid >> 2, wn = wid & 3;
    const int m0 = blockIdx.y * BM_, n0 = blockIdx.x * BN;
    const int z = blockIdx.z;

    const __half* __restrict__ Ah   = p.A[z];
    const __half* __restrict__ Bh   = p.B[z];
    const float*  __restrict__ bias = p.bias[z];
    float*  Cf = p.Cf[z];
    __half* Ch = p.Ch[z];

    const int NC = K >> 5;

    auto load_stage = [&](int chunk, int stage) {
        const long ka = (long)chunk * 32;
        const uint32_t sbase = smb + stage * STAGE;
        #pragma unroll
        for (int idx = t; idx < BM_ * 4; idx += 256) {
            const int row = idx >> 2, c = idx & 3;
            cpasync16(sbase + row * RS + c * 16,
                      Ah + (long)(m0 + row) * lda + ka + c * 8);
        }
        #pragma unroll
        for (int idx = t; idx < BN * 4; idx += 256) {
            const int row = idx >> 2, c = idx & 3;
            cpasync16(sbase + SA + row * RS + c * 16,
                      Bh + (long)(n0 + row) * ldb + ka + c * 8);
        }
        CP_COMMIT();
    };

    float acc[MT][4][4] = {};

    load_stage(0, 0);
    if (NC > 1) load_stage(1, 1);

    for (int c = 0; c < NC; c++) {
        if (c + 2 < NC) { load_stage(c + 2, (c + 2) % 3); CP_WAIT2(); }
        else if (c + 1 < NC) CP_WAIT1();
        else CP_WAIT0();
        __syncthreads();

        const uint32_t sbase = smb + (c % 3) * STAGE;

        #pragma unroll
        for (int ks = 0; ks < 2; ks++) {
            const uint32_t koff = ks * 32 + (lane >> 4) * 16;

            uint32_t ah[MT][4];
            #pragma unroll
            for (int mi = 0; mi < MT; mi++) {
                const int row = wm * WM + mi * 16 + (lane & 15);
                ldsm4(ah[mi], sbase + row * RS + koff);
            }

            uint32_t bh[4][2];
            #pragma unroll
            for (int nj = 0; nj < 2; nj++) {
                const int row = wn * 32 + nj * 16 + (lane & 15);
                uint32_t r[4];
                ldsm4(r, sbase + SA + row * RS + koff);
                bh[2*nj][0]   = r[0]; bh[2*nj][1]   = r[2];
                bh[2*nj+1][0] = r[1]; bh[2*nj+1][1] = r[3];
            }

            #pragma unroll
            for (int mi = 0; mi < MT; mi++)
                #pragma unroll
                for (int nt = 0; nt < 4; nt++)
                    mma16816(acc[mi][nt], ah[mi], bh[nt]);
        }
        __syncthreads();
    }

    const int gid = lane >> 2, tig = lane & 3;
    #pragma unroll
    for (int mi = 0; mi < MT; mi++) {
        #pragma unroll
        for (int nt = 0; nt < 4; nt++) {
            const int col = n0 + wn * 32 + nt * 8 + tig * 2;
            float2 bb = *(const float2*)(bias + col);
            #pragma unroll
            for (int h = 0; h < 2; h++) {
                const int row = m0 + wm * WM + mi * 16 + gid + h * 8;
                float vx = acc[mi][nt][2*h+0] + bb.x;
                float vy = acc[mi][nt][2*h+1] + bb.y;
                if (RELU) { vx = fmaxf(vx, 0.f); vy = fmaxf(vy, 0.f); }
                const long off = (long)row * ldc + col;
                if (!HALF_OUT) {
                    *(float2*)(Cf + off) = make_float2(vx, vy);
                } else {
                    __half2 hh;
                    hh.x = __float2half_rn(vx);
                    hh.y = __float2half_rn(vy);
                    *(__half2*)(Ch + off) = hh;
                }
            }
        }
    }
}

// ===========================================================================
// Fused dual-stream attention (flash-style), q-tile = 128 rows, 512 threads.
// Warps 0-7: img stream (w8 = wid&7 -> rows w8*16..w8*16+15).
// Warps 8-15: dpt stream. Per-warp math identical to the 64-row version —
// only CTA->row mapping changed, so results are bit-identical. K/V global
// traffic halves (512 CTAs instead of 1024 re-reading all K/V).
// ===========================================================================
__global__ __launch_bounds__(512) void flash_kernel(
    const __half* __restrict__ Qi, const __half* __restrict__ Ki,
    const __half* __restrict__ Qd, const __half* __restrict__ Kd,
    const __half* __restrict__ Vi, const __half* __restrict__ Vd,
    __half* __restrict__ Oi, __half* __restrict__ Od)
{
    constexpr int RS2 = 144;
    constexpr int TQ  = 128 * RS2;        // 18432: one stream's 128-row Q tile
    constexpr int TK  = 64 * RS2;         // 9216: one 64-key tile
    constexpr int ST_OFF = 2 * TQ;        // 36864
    constexpr int STG = 4 * TK;           // 36864 per stage (K, Kd, V, Vd)

    extern __shared__ char sm[];
    const uint32_t smb = smem_u32(sm);

    const int t = threadIdx.x, lane = t & 31, wid = t >> 5;
    const int g = wid >> 3, w8 = wid & 7;
    const int z = blockIdx.y;
    const long base  = (long)z * 64;
    const int q0 = blockIdx.x * 128;
    const float scale = 0.125f;

    // ---- load Q tiles (both streams), 128 rows each ----
    for (int idx = t; idx < 128 * 8; idx += 512) {
        const int row = idx >> 3, c = idx & 7;
        const long ga = base + (long)(q0 + row) * 4096 + c * 8;
        cpasync16(smb +      row * RS2 + c * 16, Qi + ga);
        cpasync16(smb + TQ + row * RS2 + c * 16, Qd + ga);
    }
    CP_COMMIT();

    auto load_stage = [&](int kb, int st) {
        const uint32_t sb = smb + ST_OFF + st * STG;
        for (int idx = t; idx < 64 * 8; idx += 512) {
            const int row = idx >> 3, c = idx & 7;
            const long ga = base + (long)(kb * 64 + row) * 4096 + c * 8;
            cpasync16(sb +         row * RS2 + c * 16, Ki + ga);
            cpasync16(sb +   TK +  row * RS2 + c * 16, Kd + ga);
            cpasync16(sb + 2*TK +  row * RS2 + c * 16, Vi + ga);
            cpasync16(sb + 3*TK +  row * RS2 + c * 16, Vd + ga);
        }
        CP_COMMIT();
    };

    load_stage(0, 0);
    CP_WAIT1();
    __syncthreads();

    uint32_t aq[4][4];
    {
        const uint32_t qsm = smb + g * TQ;
        const int row = w8 * 16 + (lane & 15);
        #pragma unroll
        for (int c = 0; c < 4; c++)
            ldsm4(aq[c], qsm + row * RS2 + c * 32 + (lane >> 4) * 16);
    }

    float uv[8][4] = {};
    float ud[8][4] = {};
    float ls0 = 0.f, ls1 = 0.f;

    for (int kb = 0; kb < 16; kb++) {
        if (kb + 1 < 16) { load_stage(kb + 1, (kb + 1) & 1); CP_WAIT1(); }
        else CP_WAIT0();
        __syncthreads();

        const uint32_t sb  = smb + ST_OFF + (kb & 1) * STG;
        const uint32_t ksm = sb + g * TK;
        const uint32_t vi  = sb + 2 * TK;
        const uint32_t vd  = sb + 3 * TK;
        const int lrow = lane & 15;
        const uint32_t lk = (lane >> 4) * 16;

        // ---- S = Q · K^T ----
        float s[8][4] = {};
        #pragma unroll
        for (int c = 0; c < 4; c++) {
            uint32_t bk[8][2];
            #pragma unroll
            for (int nj = 0; nj < 4; nj++) {
                uint32_t r[4];
                ldsm4(r, ksm + (nj * 16 + lrow) * RS2 + c * 32 + lk);
                bk[2*nj][0]   = r[0]; bk[2*nj][1]   = r[2];
                bk[2*nj+1][0] = r[1]; bk[2*nj+1][1] = r[3];
            }
            #pragma unroll
            for (int nt = 0; nt < 8; nt++) mma16816(s[nt], aq[c], bk[nt]);
        }

        // ---- exp + pack into A-fragments ----
        uint32_t pa[4][4];
        #pragma unroll
        for (int nt = 0; nt < 8; nt++) {
            float e0 = __expf(s[nt][0] * scale);
            float e1 = __expf(s[nt][1] * scale);
            float e2 = __expf(s[nt][2] * scale);
            float e3 = __expf(s[nt][3] * scale);
            ls0 += e0 + e1;
            ls1 += e2 + e3;
            __half2 p01 = __floats2half2_rn(e0, e1);
            __half2 p23 = __floats2half2_rn(e2, e3);
            pa[nt >> 1][(nt & 1) * 2 + 0] = *(uint32_t*)&p01;
            pa[nt >> 1][(nt & 1) * 2 + 1] = *(uint32_t*)&p23;
        }

        // ---- U += P · V (trans-ldmatrix builds B from row-major V) ----
        #pragma unroll
        for (int c = 0; c < 4; c++) {
            uint32_t bv[8][2];
            #pragma unroll
            for (int ng = 0; ng < 4; ng++) {
                uint32_t r[4];
                ldsm4t(r, vi + (c * 16 + lrow) * RS2 + ng * 32 + lk);
                bv[2*ng][0]   = r[0]; bv[2*ng][1]   = r[1];
                bv[2*ng+1][0] = r[2]; bv[2*ng+1][1] = r[3];
            }
            #pragma unroll
            for (int nt = 0; nt < 8; nt++) mma16816(uv[nt], pa[c], bv[nt]);
            #pragma unroll
            for (int ng = 0; ng < 4; ng++) {
                uint32_t r[4];
                ldsm4t(r, vd + (c * 16 + lrow) * RS2 + ng * 32 + lk);
                bv[2*ng][0]   = r[0]; bv[2*ng][1]   = r[1];
                bv[2*ng+1][0] = r[2]; bv[2*ng+1][1] = r[3];
            }
            #pragma unroll
            for (int nt = 0; nt < 8; nt++) mma16816(ud[nt], pa[c], bv[nt]);
        }
        __syncthreads();
    }

    ls0 += __shfl_xor_sync(0xffffffffu, ls0, 1);
    ls0 += __shfl_xor_sync(0xffffffffu, ls0, 2);
    ls1 += __shfl_xor_sync(0xffffffffu, ls1, 1);
    ls1 += __shfl_xor_sync(0xffffffffu, ls1, 2);
    const float inv0 = 0.5f / ls0;
    const float inv1 = 0.5f / ls1;

    // ---- combine groups via smem epilogue ([128][68] per stream) ----
    __syncthreads();
    float* so_i = (float*)sm;
    float* so_d = (float*)(sm + 128 * 68 * 4);
    const int gid = lane >> 2, tig = lane & 3;
    const int r0 = w8 * 16 + gid;

    if (g == 0) {
        #pragma unroll
        for (int nt = 0; nt < 8; nt++) {
            const int col = nt * 8 + tig * 2;
            so_i[ r0      * 68 + col]     = uv[nt][0] * inv0;
            so_i[ r0      * 68 + col + 1] = uv[nt][1] * inv0;
            so_i[(r0 + 8) * 68 + col]     = uv[nt][2] * inv1;
            so_i[(r0 + 8) * 68 + col + 1] = uv[nt][3] * inv1;
            so_d[ r0      * 68 + col]     = ud[nt][0] * inv0;
            so_d[ r0      * 68 + col + 1] = ud[nt][1] * inv0;
            so_d[(r0 + 8) * 68 + col]     = ud[nt][2] * inv1;
            so_d[(r0 + 8) * 68 + col + 1] = ud[nt][3] * inv1;
        }
    }
    __syncthreads();
    if (g == 1) {
        #pragma unroll
        for (int nt = 0; nt < 8; nt++) {
            const int col = nt * 8 + tig * 2;
            const long oa0 = base + (long)(q0 + r0)     * 4096 + col;
            const long oa1 = base + (long)(q0 + r0 + 8) * 4096 + col;
            __half2 h;
            h.x = __float2half_rn(so_i[ r0      * 68 + col]     + uv[nt][0] * inv0);
            h.y = __float2half_rn(so_i[ r0      * 68 + col + 1] + uv[nt][1] * inv0);
            *(__half2*)(Oi + oa0) = h;
            h.x = __float2half_rn(so_i[(r0 + 8) * 68 + col]     + uv[nt][2] * inv1);
            h.y = __float2half_rn(so_i[(r0 + 8) * 68 + col + 1] + uv[nt][3] * inv1);
            *(__half2*)(Oi + oa1) = h;
            h.x = __float2half_rn(so_d[ r0      * 68 + col]     + ud[nt][0] * inv0);
            h.y = __float2half_rn(so_d[ r0      * 68 + col + 1] + ud[nt][1] * inv0);
            *(__half2*)(Od + oa0) = h;
            h.x = __float2half_rn(so_d[(r0 + 8) * 68 + col]     + ud[nt][2] * inv1);
            h.y = __float2half_rn(so_d[(r0 + 8) * 68 + col + 1] + ud[nt][3] * inv1);
            *(__half2*)(Od + oa1) = h;
        }
    }
}

// ===========================================================================
// Elementwise kernels
// ===========================================================================
struct CV18 { const float* a[18]; const float* b[18]; __half* dst[18]; };
__global__ __launch_bounds__(256) void conv18_kernel(CV18 w)
{
    const int seg = blockIdx.x >> 10;
    const long i = ((long)(blockIdx.x & 1023) * 256 + threadIdx.x) * 4;
    const float* xa = w.a[seg];
    const float* xb = w.b[seg];
    __half* h = w.dst[seg];
    float4 v = *(const float4*)(xa + i);
    if (xb) {
        float4 u = *(const float4*)(xb + i);
        v.x += u.x; v.y += u.y; v.z += u.z; v.w += u.w;
    }
    __half2 h01, h23;
    h01.x = __float2half_rn(v.x); h01.y = __float2half_rn(v.y);
    h23.x = __float2half_rn(v.z); h23.y = __float2half_rn(v.w);
    *(__half2*)(h + i)     = h01;
    *(__half2*)(h + i + 2) = h23;
}

__global__ __launch_bounds__(128) void add_ln2_kernel(
    const float* __restrict__ x0, const float* __restrict__ x1,
    const float* __restrict__ y,
    const float* __restrict__ ga0, const float* __restrict__ be0,
    const float* __restrict__ ga1, const float* __restrict__ be1,
    float* __restrict__ outf, __half* __restrict__ outh)
{
    const long n = blockIdx.x;
    const int zz = n >= N_;
    const long local = zz ? n - N_ : n;
    const int t = threadIdx.x;

    const float* x = (zz ? x1 : x0) + local * D_;
    const float* gamma = zz ? ga1 : ga0;
    const float* beta  = zz ? be1 : be0;

    float4 a = ((const float4*)x)[t];
    float4 c = ((const float4*)(y + n * D_))[t];
    float v0 = a.x + c.x, v1 = a.y + c.y, v2 = a.z + c.z, v3 = a.w + c.w;

    float s  = v0 + v1 + v2 + v3;
    float sq = v0 * v0 + v1 * v1 + v2 * v2 + v3 * v3;

    __shared__ float sh[2][4];
    #pragma unroll
    for (int o = 16; o > 0; o >>= 1) {
        s  += __shfl_xor_sync(0xffffffffu, s,  o);
        sq += __shfl_xor_sync(0xffffffffu, sq, o);
    }
    if ((t & 31) == 0) { sh[0][t >> 5] = s; sh[1][t >> 5] = sq; }
    __syncthreads();
    s  = sh[0][0] + sh[0][1] + sh[0][2] + sh[0][3];
    sq = sh[1][0] + sh[1][1] + sh[1][2] + sh[1][3];

    const float mean = s * (1.0f / D_);
    const float var  = sq * (1.0f / D_) - mean * mean;
    const float inv  = rsqrtf(var + 1e-5f);

    float4 gg = ((const float4*)gamma)[t];
    float4 bb = ((const float4*)beta)[t];
    float4 o4;
    o4.x = (v0 - mean) * inv * gg.x + bb.x;
    o4.y = (v1 - mean) * inv * gg.y + bb.y;
    o4.z = (v2 - mean) * inv * gg.z + bb.z;
    o4.w = (v3 - mean) * inv * gg.w + bb.w;
    ((float4*)(outf + n * D_))[t] = o4;
    if (outh) {
        long i = n * D_ + t * 4;
        __half2 h01, h23;
        h01.x = __float2half_rn(o4.x); h01.y = __float2half_rn(o4.y);
        h23.x = __float2half_rn(o4.z); h23.y = __float2half_rn(o4.w);
        *(__half2*)(outh + i)     = h01;
        *(__half2*)(outh + i + 2) = h23;
    }
}

// ===========================================================================
// Launch
// ===========================================================================
#define SYM(p, s) do { void* _q; cudaGetSymbolAddress(&_q, s); p = (decltype(p))_q; } while (0)

extern "C" void kernel_launch(void* const* d_in, const int* in_sizes, int n_in,
                              void* d_out, int out_size)
{
    const float* src  = (const float*)d_in[0];
    const float* srcd = (const float*)d_in[1];
    const float* pos  = (const float*)d_in[2];
    const float* wi   = (const float*)d_in[3];
    const float* bi   = (const float*)d_in[4];
    const float* wd   = (const float*)d_in[5];
    const float* bd   = (const float*)d_in[6];
    const float* w1i  = (const float*)d_in[7];
    const float* b1i  = (const float*)d_in[8];
    const float* w2i  = (const float*)d_in[9];
    const float* b2i  = (const float*)d_in[10];
    const float* w1d  = (const float*)d_in[11];
    const float* b1d  = (const float*)d_in[12];
    const float* w2d  = (const float*)d_in[13];
    const float* b2d  = (const float*)d_in[14];
    const float* lni  = (const float*)d_in[15];
    const float* lnd  = (const float*)d_in[16];
    float* out = (float*)d_out;

    __half *wih,*wdh,*w1ih,*w2ih,*w1dh,*w2dh;
    __half *qkinh,*srch,*srcdh;
    __half *qh,*qdh,*kh,*kdh,*vh,*vdh;
    __half *oih,*odh,*x2h,*ff2;
    float *t2,*x2;

    SYM(wih, g_wih);   SYM(wdh, g_wdh);
    SYM(w1ih, g_w1ih); SYM(w2ih, g_w2ih);
    SYM(w1dh, g_w1dh); SYM(w2dh, g_w2dh);
    SYM(qkinh, g_qkinh);
    SYM(srch, g_srch); SYM(srcdh, g_srcdh);
    SYM(qh, g_qh); SYM(qdh, g_qdh);
    SYM(kh, g_kh); SYM(kdh, g_kdh);
    SYM(vh, g_vh); SYM(vdh, g_vdh);
    SYM(oih, g_oih); SYM(odh, g_odh);
    SYM(t2, g_t2); SYM(x2, g_x2); SYM(x2h, g_x2h);
    SYM(ff2, g_ff2);

    constexpr int SMEM_G128 = 3 * (128 * 80 + 128 * 80);           // 61440
    constexpr int SMEM_G64  = 3 * ( 64 * 80 + 128 * 80);           // 46080
    constexpr int SMEM_FLASH = 2 * (128 * 144) + 2 * (4 * 64 * 144); // 110592
    cudaFuncSetAttribute((const void*)&mma_gemm<6,128,false,true>,
                         cudaFuncAttributeMaxDynamicSharedMemorySize, SMEM_G128);
    cudaFuncSetAttribute((const void*)&mma_gemm<2,128,true,true>,
                         cudaFuncAttributeMaxDynamicSharedMemorySize, SMEM_G128);
    cudaFuncSetAttribute((const void*)&mma_gemm<2,64,false,false>,
                         cudaFuncAttributeMaxDynamicSharedMemorySize, SMEM_G64);
    cudaFuncSetAttribute((const void*)&flash_kernel,
                         cudaFuncAttributeMaxDynamicSharedMemorySize, SMEM_FLASH);

    // --- ALL conversions (weights + activations) in ONE launch ---
    {
        CV18 w{};
        w.a[0] = wi;   w.dst[0] = wih;
        w.a[1] = wd;   w.dst[1] = wdh;
        w.a[2] = w1i;  w.dst[2] = w1ih;
        w.a[3] = w2i;  w.dst[3] = w2ih;
        w.a[4] = w1d;  w.dst[4] = w1dh;
        w.a[5] = w2d;  w.dst[5] = w2dh;
        #pragma unroll
        for (int s = 0; s < 4; s++) {
            w.a[6 + s]  = src  + ((long)s << 20); w.b[6 + s] = pos + ((long)s << 20);
            w.dst[6 + s] = qkinh + ((long)s << 20);
            w.a[10 + s] = src  + ((long)s << 20); w.dst[10 + s] = srch  + ((long)s << 20);
            w.a[14 + s] = srcd + ((long)s << 20); w.dst[14 + s] = srcdh + ((long)s << 20);
        }
        conv18_kernel<<<18 * 1024, 256>>>(w);
    }

    // --- all six projections in ONE z=6 launch ---
    {
        GP<6> p{};
        p.A[0] = qkinh; p.B[0] = wih;          p.bias[0] = bi;          p.Ch[0] = qh;
        p.A[1] = qkinh; p.B[1] = wih + DD_;    p.bias[1] = bi + D_;     p.Ch[1] = kh;
        p.A[2] = srch;  p.B[2] = wih + 2*DD_;  p.bias[2] = bi + 2*D_;   p.Ch[2] = vh;
        p.A[3] = srcdh; p.B[3] = wdh;          p.bias[3] = bd;          p.Ch[3] = qdh;
        p.A[4] = srcdh; p.B[4] = wdh + DD_;    p.bias[4] = bd + D_;     p.Ch[4] = kdh;
        p.A[5] = srcdh; p.B[5] = wdh + 2*DD_;  p.bias[5] = bd + 2*D_;   p.Ch[5] = vdh;
        dim3 gProj(D_ / 128, N_ / 128, 6);
        mma_gemm<6,128,false,true><<<gProj,256,SMEM_G128>>>(p, D_, D_, D_, D_);
    }

    // --- fused attention (q-tile 128, 512 threads) ---
    dim3 gFl(S_ / 128, NH_, 1);
    flash_kernel<<<gFl, 512, SMEM_FLASH>>>(qh, kh, qdh, kdh, vh, vdh, oih, odh);

    // --- out-proj (z=2, BM=64) -> t2 fp32 ---
    {
        GP<2> p{};
        p.A[0] = oih; p.B[0] = wih + 3*DD_; p.bias[0] = bi + 3*D_; p.Cf[0] = t2;
        p.A[1] = odh; p.B[1] = wdh + 3*DD_; p.bias[1] = bd + 3*D_; p.Cf[1] = t2 + (long)N_*D_;
        dim3 gr(D_ / 128, N_ / 64, 2);
        mma_gemm<2,64,false,false><<<gr,256,SMEM_G64>>>(p, D_, D_, D_, D_);
    }
    // --- LN1 ---
    add_ln2_kernel<<<2*N_,128>>>(src, srcd, t2,
        lni, lni + D_, lnd, lnd + D_, x2, x2h);
    // --- FFN1 (+ReLU) (z=2) ---
    {
        GP<2> p{};
        p.A[0] = x2h;               p.B[0] = w1ih; p.bias[0] = b1i; p.Ch[0] = ff2;
        p.A[1] = x2h + (long)N_*D_; p.B[1] = w1dh; p.bias[1] = b1d; p.Ch[1] = ff2 + (long)N_*FF_;
        dim3 gr(FF_ / 128, N_ / 128, 2);
        mma_gemm<2,128,true,true><<<gr,256,SMEM_G128>>>(p, D_, D_, D_, FF_);
    }
    // --- FFN2 (z=2, BM=64) -> t2 fp32 ---
    {
        GP<2> p{};
        p.A[0] = ff2;                p.B[0] = w2ih; p.bias[0] = b2i; p.Cf[0] = t2;
        p.A[1] = ff2 + (long)N_*FF_; p.B[1] = w2dh; p.bias[1] = b2d; p.Cf[1] = t2 + (long)N_*D_;
        dim3 gr(D_ / 128, N_ / 64, 2);
        mma_gemm<2,64,false,false><<<gr,256,SMEM_G64>>>(p, FF_, FF_, FF_, D_);
    }
    // --- LN2 -> out ---
    add_ln2_kernel<<<2*N_,128>>>(x2, x2 + (long)N_*D_, t2,
        lni + 2*D_, lni + 3*D_, lnd + 2*D_, lnd + 3*D_, out, nullptr);
}

// round 13
// speedup vs baseline: 1.0318x; 1.0318x over previous
#include <cuda_runtime.h>
#include <cuda_fp16.h>
#include <math.h>
#include <stdint.h>

// Problem constants
#define S_   1024
#define B_   8
#define D_   512
#define H_   8
#define HD_  64
#define FF_  2048
#define N_   (S_ * B_)      // 8192 tokens
#define NH_  (B_ * H_)      // 64 (batch*heads)
#define DD_  (D_ * D_)

// ===========================================================================
// PTX helpers — baseline-PTX only (compute_103 virtual arch: NO tcgen05)
// ===========================================================================
__device__ __forceinline__ uint32_t smem_u32(const void* p) {
    uint32_t a;
    asm("{ .reg .u64 t; cvta.to.shared.u64 t, %1; cvt.u32.u64 %0, t; }" : "=r"(a) : "l"(p));
    return a;
}

__device__ __forceinline__ void cpasync16(uint32_t s, const void* g) {
    asm volatile("cp.async.cg.shared.global [%0], [%1], 16;" :: "r"(s), "l"(g));
}
#define CP_COMMIT()  asm volatile("cp.async.commit_group;" ::: "memory")
#define CP_WAIT0()   asm volatile("cp.async.wait_group 0;" ::: "memory")
#define CP_WAIT1()   asm volatile("cp.async.wait_group 1;" ::: "memory")
#define CP_WAIT2()   asm volatile("cp.async.wait_group 2;" ::: "memory")

__device__ __forceinline__ void ldsm4(uint32_t r[4], uint32_t addr) {
    asm volatile("ldmatrix.sync.aligned.m8n8.x4.shared.b16 {%0,%1,%2,%3}, [%4];"
        : "=r"(r[0]), "=r"(r[1]), "=r"(r[2]), "=r"(r[3]) : "r"(addr));
}

// Transposing ldmatrix: for row-major [K,N] tiles used as B operands.
__device__ __forceinline__ void ldsm4t(uint32_t r[4], uint32_t addr) {
    asm volatile("ldmatrix.sync.aligned.m8n8.x4.trans.shared.b16 {%0,%1,%2,%3}, [%4];"
        : "=r"(r[0]), "=r"(r[1]), "=r"(r[2]), "=r"(r[3]) : "r"(addr));
}

// fp16 MMA, fp32 accumulate
__device__ __forceinline__ void mma16816(float acc[4], const uint32_t a[4], const uint32_t b[2]) {
    asm volatile(
        "mma.sync.aligned.m16n8k16.row.col.f32.f16.f16.f32 "
        "{%0,%1,%2,%3}, {%4,%5,%6,%7}, {%8,%9}, {%0,%1,%2,%3};"
        : "+f"(acc[0]), "+f"(acc[1]), "+f"(acc[2]), "+f"(acc[3])
        : "r"(a[0]), "r"(a[1]), "r"(a[2]), "r"(a[3]), "r"(b[0]), "r"(b[1]));
}

// ===========================================================================
// Scratch (static device memory)
// ===========================================================================
__device__ __half g_wih[4*DD_], g_wdh[4*DD_];
__device__ __half g_w1ih[FF_*D_], g_w2ih[D_*FF_];
__device__ __half g_w1dh[FF_*D_], g_w2dh[D_*FF_];
__device__ __half g_qkinh[N_*D_];
__device__ __half g_srch[N_*D_], g_srcdh[N_*D_];
__device__ __half g_qh[N_*D_],  g_qdh[N_*D_];
__device__ __half g_kh[N_*D_],  g_kdh[N_*D_];
__device__ __half g_vh[N_*D_],  g_vdh[N_*D_];
__device__ __half g_oih[N_*D_], g_odh[N_*D_];
__device__ float  g_t2[2*N_*D_];
__device__ float  g_x2[2*N_*D_];
__device__ __half g_x2h[2*N_*D_];
__device__ __half g_ff2[2*N_*FF_];

// ===========================================================================
// Z-batched mma.sync GEMM (R10 known-good config):
//   C_z[M,N] = A_z[M,K] * B_z[N,K]^T + bias_z
// BM_ in {128, 64}; BN=128; BK=32. 256 threads = 8 warps (2x4), 64x32 warp tile.
// 3-stage cp.async pipeline; 80B padded smem rows (conflict-free ldmatrix).
// ===========================================================================
template<int NZ>
struct GP {
    const __half* A[NZ];
    const __half* B[NZ];
    const float*  bias[NZ];
    float*        Cf[NZ];
    __half*       Ch[NZ];
};

template<int NZ, int BM_, bool RELU, bool HALF_OUT>
__global__ __launch_bounds__(256) void mma_gemm(
    GP<NZ> p, int K, int lda, int ldb, int ldc)
{
    constexpr int BN = 128;
    constexpr int WM = BM_ / 2;
    constexpr int MT = WM / 16;
    constexpr int RS = 80;
    constexpr int SA = BM_ * RS;
    constexpr int STAGE = SA + BN * RS;

    extern __shared__ char sm[];
    const uint32_t smb = smem_u32(sm);

    const int t = threadIdx.x;
    const int lane = t & 31, wid = t >> 5;
    const int wm = wid >> 2, wn = wid & 3;
    const int m0 = blockIdx.y * BM_, n0 = blockIdx.x * BN;
    const int z = blockIdx.z;

    const __half* __restrict__ Ah   = p.A[z];
    const __half* __restrict__ Bh   = p.B[z];
    const float*  __restrict__ bias = p.bias[z];
    float*  Cf = p.Cf[z];
    __half* Ch = p.Ch[z];

    const int NC = K >> 5;

    auto load_stage = [&](int chunk, int stage) {
        const long ka = (long)chunk * 32;
        const uint32_t sbase = smb + stage * STAGE;
        #pragma unroll
        for (int idx = t; idx < BM_ * 4; idx += 256) {
            const int row = idx >> 2, c = idx & 3;
            cpasync16(sbase + row * RS + c * 16,
                      Ah + (long)(m0 + row) * lda + ka + c * 8);
        }
        #pragma unroll
        for (int idx = t; idx < BN * 4; idx += 256) {
            const int row = idx >> 2, c = idx & 3;
            cpasync16(sbase + SA + row * RS + c * 16,
                      Bh + (long)(n0 + row) * ldb + ka + c * 8);
        }
        CP_COMMIT();
    };

    float acc[MT][4][4] = {};

    load_stage(0, 0);
    if (NC > 1) load_stage(1, 1);

    for (int c = 0; c < NC; c++) {
        if (c + 2 < NC) { load_stage(c + 2, (c + 2) % 3); CP_WAIT2(); }
        else if (c + 1 < NC) CP_WAIT1();
        else CP_WAIT0();
        __syncthreads();

        const uint32_t sbase = smb + (c % 3) * STAGE;

        #pragma unroll
        for (int ks = 0; ks < 2; ks++) {
            const uint32_t koff = ks * 32 + (lane >> 4) * 16;

            uint32_t ah[MT][4];
            #pragma unroll
            for (int mi = 0; mi < MT; mi++) {
                const int row = wm * WM + mi * 16 + (lane & 15);
                ldsm4(ah[mi], sbase + row * RS + koff);
            }

            uint32_t bh[4][2];
            #pragma unroll
            for (int nj = 0; nj < 2; nj++) {
                const int row = wn * 32 + nj * 16 + (lane & 15);
                uint32_t r[4];
                ldsm4(r, sbase + SA + row * RS + koff);
                bh[2*nj][0]   = r[0]; bh[2*nj][1]   = r[2];
                bh[2*nj+1][0] = r[1]; bh[2*nj+1][1] = r[3];
            }

            #pragma unroll
            for (int mi = 0; mi < MT; mi++)
                #pragma unroll
                for (int nt = 0; nt < 4; nt++)
                    mma16816(acc[mi][nt], ah[mi], bh[nt]);
        }
        __syncthreads();
    }

    const int gid = lane >> 2, tig = lane & 3;
    #pragma unroll
    for (int mi = 0; mi < MT; mi++) {
        #pragma unroll
        for (int nt = 0; nt < 4; nt++) {
            const int col = n0 + wn * 32 + nt * 8 + tig * 2;
            float2 bb = *(const float2*)(bias + col);
            #pragma unroll
            for (int h = 0; h < 2; h++) {
                const int row = m0 + wm * WM + mi * 16 + gid + h * 8;
                float vx = acc[mi][nt][2*h+0] + bb.x;
                float vy = acc[mi][nt][2*h+1] + bb.y;
                if (RELU) { vx = fmaxf(vx, 0.f); vy = fmaxf(vy, 0.f); }
                const long off = (long)row * ldc + col;
                if (!HALF_OUT) {
                    *(float2*)(Cf + off) = make_float2(vx, vy);
                } else {
                    __half2 hh;
                    hh.x = __float2half_rn(vx);
                    hh.y = __float2half_rn(vy);
                    *(__half2*)(Ch + off) = hh;
                }
            }
        }
    }
}

// ===========================================================================
// Fused dual-stream attention (flash-style), q-tile 64 rows, 256 threads
// (R10 config), now with a 3-deep K/V pipeline at the SAME smem footprint:
// the Q tiles live in stage-buffer 2 only until aq fragments are extracted,
// then buffer 2 is recycled for K/V stages (kb = 2, 5, 8, ...).
// ===========================================================================
__global__ __launch_bounds__(256) void flash_kernel(
    const __half* __restrict__ Qi, const __half* __restrict__ Ki,
    const __half* __restrict__ Qd, const __half* __restrict__ Kd,
    const __half* __restrict__ Vi, const __half* __restrict__ Vd,
    __half* __restrict__ Oi, __half* __restrict__ Od)
{
    constexpr int RS2 = 144;
    constexpr int TK  = 64 * RS2;      // 9216: one 64-row tile
    constexpr int STG = 4 * TK;        // 36864 per stage (K, Kd, V, Vd)
    // total smem = 3 * STG = 110592; Q parked in stage 2 initially.

    extern __shared__ char sm[];
    const uint32_t smb = smem_u32(sm);

    const int t = threadIdx.x, lane = t & 31, wid = t >> 5;
    const int g = wid >> 2, w4 = wid & 3;
    const int z = blockIdx.y;
    const long base  = (long)z * 64;
    const int q0 = blockIdx.x * 64;
    const float scale = 0.125f;

    // ---- group Gq: Q tiles into stage-buffer 2 ----
    for (int idx = t; idx < 64 * 8; idx += 256) {
        const int row = idx >> 3, c = idx & 7;
        const long ga = base + (long)(q0 + row) * 4096 + c * 8;
        cpasync16(smb + 2 * STG +      row * RS2 + c * 16, Qi + ga);
        cpasync16(smb + 2 * STG + TK + row * RS2 + c * 16, Qd + ga);
    }
    CP_COMMIT();

    auto load_stage = [&](int kb, int st) {
        const uint32_t sb = smb + st * STG;
        for (int idx = t; idx < 64 * 8; idx += 256) {
            const int row = idx >> 3, c = idx & 7;
            const long ga = base + (long)(kb * 64 + row) * 4096 + c * 8;
            cpasync16(sb +         row * RS2 + c * 16, Ki + ga);
            cpasync16(sb +   TK +  row * RS2 + c * 16, Kd + ga);
            cpasync16(sb + 2*TK +  row * RS2 + c * 16, Vi + ga);
            cpasync16(sb + 3*TK +  row * RS2 + c * 16, Vd + ga);
        }
        CP_COMMIT();
    };

    load_stage(0, 0);      // G0
    load_stage(1, 1);      // G1
    CP_WAIT2();            // drain Gq (G0, G1 still pending)
    __syncthreads();

    // Q fragments (resident); Q smem (buffer 2) is dead after this.
    uint32_t aq[4][4];
    {
        const uint32_t qsm = smb + 2 * STG + g * TK;
        const int row = w4 * 16 + (lane & 15);
        #pragma unroll
        for (int c = 0; c < 4; c++)
            ldsm4(aq[c], qsm + row * RS2 + c * 32 + (lane >> 4) * 16);
    }
    __syncthreads();       // all warps done reading Q before buffer 2 reuse

    float uv[8][4] = {};
    float ud[8][4] = {};
    float ls0 = 0.f, ls1 = 0.f;

    for (int kb = 0; kb < 16; kb++) {
        // issue load for kb+2 into buffer (kb+2)%3 (buffer computed at kb-1,
        // protected by the trailing __syncthreads of that iteration)
        if (kb + 2 < 16) { load_stage(kb + 2, (kb + 2) % 3); CP_WAIT2(); }
        else if (kb + 1 < 16) CP_WAIT1();
        else CP_WAIT0();
        __syncthreads();

        const uint32_t sb  = smb + (kb % 3) * STG;
        const uint32_t ksm = sb + g * TK;
        const uint32_t vi  = sb + 2 * TK;
        const uint32_t vd  = sb + 3 * TK;
        const int lrow = lane & 15;
        const uint32_t lk = (lane >> 4) * 16;

        // ---- S = Q · K^T ----
        float s[8][4] = {};
        #pragma unroll
        for (int c = 0; c < 4; c++) {
            uint32_t bk[8][2];
            #pragma unroll
            for (int nj = 0; nj < 4; nj++) {
                uint32_t r[4];
                ldsm4(r, ksm + (nj * 16 + lrow) * RS2 + c * 32 + lk);
                bk[2*nj][0]   = r[0]; bk[2*nj][1]   = r[2];
                bk[2*nj+1][0] = r[1]; bk[2*nj+1][1] = r[3];
            }
            #pragma unroll
            for (int nt = 0; nt < 8; nt++) mma16816(s[nt], aq[c], bk[nt]);
        }

        // ---- exp + pack into A-fragments ----
        uint32_t pa[4][4];
        #pragma unroll
        for (int nt = 0; nt < 8; nt++) {
            float e0 = __expf(s[nt][0] * scale);
            float e1 = __expf(s[nt][1] * scale);
            float e2 = __expf(s[nt][2] * scale);
            float e3 = __expf(s[nt][3] * scale);
            ls0 += e0 + e1;
            ls1 += e2 + e3;
            __half2 p01 = __floats2half2_rn(e0, e1);
            __half2 p23 = __floats2half2_rn(e2, e3);
            pa[nt >> 1][(nt & 1) * 2 + 0] = *(uint32_t*)&p01;
            pa[nt >> 1][(nt & 1) * 2 + 1] = *(uint32_t*)&p23;
        }

        // ---- U += P · V (trans-ldmatrix builds B from row-major V) ----
        #pragma unroll
        for (int c = 0; c < 4; c++) {
            uint32_t bv[8][2];
            #pragma unroll
            for (int ng = 0; ng < 4; ng++) {
                uint32_t r[4];
                ldsm4t(r, vi + (c * 16 + lrow) * RS2 + ng * 32 + lk);
                bv[2*ng][0]   = r[0]; bv[2*ng][1]   = r[1];
                bv[2*ng+1][0] = r[2]; bv[2*ng+1][1] = r[3];
            }
            #pragma unroll
            for (int nt = 0; nt < 8; nt++) mma16816(uv[nt], pa[c], bv[nt]);
            #pragma unroll
            for (int ng = 0; ng < 4; ng++) {
                uint32_t r[4];
                ldsm4t(r, vd + (c * 16 + lrow) * RS2 + ng * 32 + lk);
                bv[2*ng][0]   = r[0]; bv[2*ng][1]   = r[1];
                bv[2*ng+1][0] = r[2]; bv[2*ng+1][1] = r[3];
            }
            #pragma unroll
            for (int nt = 0; nt < 8; nt++) mma16816(ud[nt], pa[c], bv[nt]);
        }
        __syncthreads();
    }

    ls0 += __shfl_xor_sync(0xffffffffu, ls0, 1);
    ls0 += __shfl_xor_sync(0xffffffffu, ls0, 2);
    ls1 += __shfl_xor_sync(0xffffffffu, ls1, 1);
    ls1 += __shfl_xor_sync(0xffffffffu, ls1, 2);
    const float inv0 = 0.5f / ls0;
    const float inv1 = 0.5f / ls1;

    // ---- combine groups via smem epilogue ----
    __syncthreads();
    float* so_i = (float*)sm;
    float* so_d = (float*)(sm + 64 * 68 * 4);
    const int gid = lane >> 2, tig = lane & 3;
    const int r0 = w4 * 16 + gid;

    if (g == 0) {
        #pragma unroll
        for (int nt = 0; nt < 8; nt++) {
            const int col = nt * 8 + tig * 2;
            so_i[ r0      * 68 + col]     = uv[nt][0] * inv0;
            so_i[ r0      * 68 + col + 1] = uv[nt][1] * inv0;
            so_i[(r0 + 8) * 68 + col]     = uv[nt][2] * inv1;
            so_i[(r0 + 8) * 68 + col + 1] = uv[nt][3] * inv1;
            so_d[ r0      * 68 + col]     = ud[nt][0] * inv0;
            so_d[ r0      * 68 + col + 1] = ud[nt][1] * inv0;
            so_d[(r0 + 8) * 68 + col]     = ud[nt][2] * inv1;
            so_d[(r0 + 8) * 68 + col + 1] = ud[nt][3] * inv1;
        }
    }
    __syncthreads();
    if (g == 1) {
        #pragma unroll
        for (int nt = 0; nt < 8; nt++) {
            const int col = nt * 8 + tig * 2;
            const long oa0 = base + (long)(q0 + r0)     * 4096 + col;
            const long oa1 = base + (long)(q0 + r0 + 8) * 4096 + col;
            __half2 h;
            h.x = __float2half_rn(so_i[ r0      * 68 + col]     + uv[nt][0] * inv0);
            h.y = __float2half_rn(so_i[ r0      * 68 + col + 1] + uv[nt][1] * inv0);
            *(__half2*)(Oi + oa0) = h;
            h.x = __float2half_rn(so_i[(r0 + 8) * 68 + col]     + uv[nt][2] * inv1);
            h.y = __float2half_rn(so_i[(r0 + 8) * 68 + col + 1] + uv[nt][3] * inv1);
            *(__half2*)(Oi + oa1) = h;
            h.x = __float2half_rn(so_d[ r0      * 68 + col]     + ud[nt][0] * inv0);
            h.y = __float2half_rn(so_d[ r0      * 68 + col + 1] + ud[nt][1] * inv0);
            *(__half2*)(Od + oa0) = h;
            h.x = __float2half_rn(so_d[(r0 + 8) * 68 + col]     + ud[nt][2] * inv1);
            h.y = __float2half_rn(so_d[(r0 + 8) * 68 + col + 1] + ud[nt][3] * inv1);
            *(__half2*)(Od + oa1) = h;
        }
    }
}

// ===========================================================================
// Elementwise kernels
// ===========================================================================
struct CV18 { const float* a[18]; const float* b[18]; __half* dst[18]; };
__global__ __launch_bounds__(256) void conv18_kernel(CV18 w)
{
    const int seg = blockIdx.x >> 10;
    const long i = ((long)(blockIdx.x & 1023) * 256 + threadIdx.x) * 4;
    const float* xa = w.a[seg];
    const float* xb = w.b[seg];
    __half* h = w.dst[seg];
    float4 v = *(const float4*)(xa + i);
    if (xb) {
        float4 u = *(const float4*)(xb + i);
        v.x += u.x; v.y += u.y; v.z += u.z; v.w += u.w;
    }
    __half2 h01, h23;
    h01.x = __float2half_rn(v.x); h01.y = __float2half_rn(v.y);
    h23.x = __float2half_rn(v.z); h23.y = __float2half_rn(v.w);
    *(__half2*)(h + i)     = h01;
    *(__half2*)(h + i + 2) = h23;
}

__global__ __launch_bounds__(128) void add_ln2_kernel(
    const float* __restrict__ x0, const float* __restrict__ x1,
    const float* __restrict__ y,
    const float* __restrict__ ga0, const float* __restrict__ be0,
    const float* __restrict__ ga1, const float* __restrict__ be1,
    float* __restrict__ outf, __half* __restrict__ outh)
{
    const long n = blockIdx.x;
    const int zz = n >= N_;
    const long local = zz ? n - N_ : n;
    const int t = threadIdx.x;

    const float* x = (zz ? x1 : x0) + local * D_;
    const float* gamma = zz ? ga1 : ga0;
    const float* beta  = zz ? be1 : be0;

    float4 a = ((const float4*)x)[t];
    float4 c = ((const float4*)(y + n * D_))[t];
    float v0 = a.x + c.x, v1 = a.y + c.y, v2 = a.z + c.z, v3 = a.w + c.w;

    float s  = v0 + v1 + v2 + v3;
    float sq = v0 * v0 + v1 * v1 + v2 * v2 + v3 * v3;

    __shared__ float sh[2][4];
    #pragma unroll
    for (int o = 16; o > 0; o >>= 1) {
        s  += __shfl_xor_sync(0xffffffffu, s,  o);
        sq += __shfl_xor_sync(0xffffffffu, sq, o);
    }
    if ((t & 31) == 0) { sh[0][t >> 5] = s; sh[1][t >> 5] = sq; }
    __syncthreads();
    s  = sh[0][0] + sh[0][1] + sh[0][2] + sh[0][3];
    sq = sh[1][0] + sh[1][1] + sh[1][2] + sh[1][3];

    const float mean = s * (1.0f / D_);
    const float var  = sq * (1.0f / D_) - mean * mean;
    const float inv  = rsqrtf(var + 1e-5f);

    float4 gg = ((const float4*)gamma)[t];
    float4 bb = ((const float4*)beta)[t];
    float4 o4;
    o4.x = (v0 - mean) * inv * gg.x + bb.x;
    o4.y = (v1 - mean) * inv * gg.y + bb.y;
    o4.z = (v2 - mean) * inv * gg.z + bb.z;
    o4.w = (v3 - mean) * inv * gg.w + bb.w;
    ((float4*)(outf + n * D_))[t] = o4;
    if (outh) {
        long i = n * D_ + t * 4;
        __half2 h01, h23;
        h01.x = __float2half_rn(o4.x); h01.y = __float2half_rn(o4.y);
        h23.x = __float2half_rn(o4.z); h23.y = __float2half_rn(o4.w);
        *(__half2*)(outh + i)     = h01;
        *(__half2*)(outh + i + 2) = h23;
    }
}

// ===========================================================================
// Launch
// ===========================================================================
#define SYM(p, s) do { void* _q; cudaGetSymbolAddress(&_q, s); p = (decltype(p))_q; } while (0)

extern "C" void kernel_launch(void* const* d_in, const int* in_sizes, int n_in,
                              void* d_out, int out_size)
{
    const float* src  = (const float*)d_in[0];
    const float* srcd = (const float*)d_in[1];
    const float* pos  = (const float*)d_in[2];
    const float* wi   = (const float*)d_in[3];
    const float* bi   = (const float*)d_in[4];
    const float* wd   = (const float*)d_in[5];
    const float* bd   = (const float*)d_in[6];
    const float* w1i  = (const float*)d_in[7];
    const float* b1i  = (const float*)d_in[8];
    const float* w2i  = (const float*)d_in[9];
    const float* b2i  = (const float*)d_in[10];
    const float* w1d  = (const float*)d_in[11];
    const float* b1d  = (const float*)d_in[12];
    const float* w2d  = (const float*)d_in[13];
    const float* b2d  = (const float*)d_in[14];
    const float* lni  = (const float*)d_in[15];
    const float* lnd  = (const float*)d_in[16];
    float* out = (float*)d_out;

    __half *wih,*wdh,*w1ih,*w2ih,*w1dh,*w2dh;
    __half *qkinh,*srch,*srcdh;
    __half *qh,*qdh,*kh,*kdh,*vh,*vdh;
    __half *oih,*odh,*x2h,*ff2;
    float *t2,*x2;

    SYM(wih, g_wih);   SYM(wdh, g_wdh);
    SYM(w1ih, g_w1ih); SYM(w2ih, g_w2ih);
    SYM(w1dh, g_w1dh); SYM(w2dh, g_w2dh);
    SYM(qkinh, g_qkinh);
    SYM(srch, g_srch); SYM(srcdh, g_srcdh);
    SYM(qh, g_qh); SYM(qdh, g_qdh);
    SYM(kh, g_kh); SYM(kdh, g_kdh);
    SYM(vh, g_vh); SYM(vdh, g_vdh);
    SYM(oih, g_oih); SYM(odh, g_odh);
    SYM(t2, g_t2); SYM(x2, g_x2); SYM(x2h, g_x2h);
    SYM(ff2, g_ff2);

    constexpr int SMEM_G128 = 3 * (128 * 80 + 128 * 80);           // 61440
    constexpr int SMEM_G64  = 3 * ( 64 * 80 + 128 * 80);           // 46080
    constexpr int SMEM_FLASH = 3 * (4 * 64 * 144);                 // 110592
    cudaFuncSetAttribute((const void*)&mma_gemm<6,128,false,true>,
                         cudaFuncAttributeMaxDynamicSharedMemorySize, SMEM_G128);
    cudaFuncSetAttribute((const void*)&mma_gemm<2,128,true,true>,
                         cudaFuncAttributeMaxDynamicSharedMemorySize, SMEM_G128);
    cudaFuncSetAttribute((const void*)&mma_gemm<2,64,false,false>,
                         cudaFuncAttributeMaxDynamicSharedMemorySize, SMEM_G64);
    cudaFuncSetAttribute((const void*)&flash_kernel,
                         cudaFuncAttributeMaxDynamicSharedMemorySize, SMEM_FLASH);

    // --- ALL conversions (weights + activations) in ONE launch ---
    {
        CV18 w{};
        w.a[0] = wi;   w.dst[0] = wih;
        w.a[1] = wd;   w.dst[1] = wdh;
        w.a[2] = w1i;  w.dst[2] = w1ih;
        w.a[3] = w2i;  w.dst[3] = w2ih;
        w.a[4] = w1d;  w.dst[4] = w1dh;
        w.a[5] = w2d;  w.dst[5] = w2dh;
        #pragma unroll
        for (int s = 0; s < 4; s++) {
            w.a[6 + s]  = src  + ((long)s << 20); w.b[6 + s] = pos + ((long)s << 20);
            w.dst[6 + s] = qkinh + ((long)s << 20);
            w.a[10 + s] = src  + ((long)s << 20); w.dst[10 + s] = srch  + ((long)s << 20);
            w.a[14 + s] = srcd + ((long)s << 20); w.dst[14 + s] = srcdh + ((long)s << 20);
        }
        conv18_kernel<<<18 * 1024, 256>>>(w);
    }

    // --- all six projections in ONE z=6 launch ---
    {
        GP<6> p{};
        p.A[0] = qkinh; p.B[0] = wih;          p.bias[0] = bi;          p.Ch[0] = qh;
        p.A[1] = qkinh; p.B[1] = wih + DD_;    p.bias[1] = bi + D_;     p.Ch[1] = kh;
        p.A[2] = srch;  p.B[2] = wih + 2*DD_;  p.bias[2] = bi + 2*D_;   p.Ch[2] = vh;
        p.A[3] = srcdh; p.B[3] = wdh;          p.bias[3] = bd;          p.Ch[3] = qdh;
        p.A[4] = srcdh; p.B[4] = wdh + DD_;    p.bias[4] = bd + D_;     p.Ch[4] = kdh;
        p.A[5] = srcdh; p.B[5] = wdh + 2*DD_;  p.bias[5] = bd + 2*D_;   p.Ch[5] = vdh;
        dim3 gProj(D_ / 128, N_ / 128, 6);
        mma_gemm<6,128,false,true><<<gProj,256,SMEM_G128>>>(p, D_, D_, D_, D_);
    }

    // --- fused attention (q-tile 64, 256 threads, 3-stage pipeline) ---
    dim3 gFl(S_ / 64, NH_, 1);
    flash_kernel<<<gFl, 256, SMEM_FLASH>>>(qh, kh, qdh, kdh, vh, vdh, oih, odh);

    // --- out-proj (z=2, BM=64) -> t2 fp32 ---
    {
        GP<2> p{};
        p.A[0] = oih; p.B[0] = wih + 3*DD_; p.bias[0] = bi + 3*D_; p.Cf[0] = t2;
        p.A[1] = odh; p.B[1] = wdh + 3*DD_; p.bias[1] = bd + 3*D_; p.Cf[1] = t2 + (long)N_*D_;
        dim3 gr(D_ / 128, N_ / 64, 2);
        mma_gemm<2,64,false,false><<<gr,256,SMEM_G64>>>(p, D_, D_, D_, D_);
    }
    // --- LN1 ---
    add_ln2_kernel<<<2*N_,128>>>(src, srcd, t2,
        lni, lni + D_, lnd, lnd + D_, x2, x2h);
    // --- FFN1 (+ReLU) (z=2) ---
    {
        GP<2> p{};
        p.A[0] = x2h;               p.B[0] = w1ih; p.bias[0] = b1i; p.Ch[0] = ff2;
        p.A[1] = x2h + (long)N_*D_; p.B[1] = w1dh; p.bias[1] = b1d; p.Ch[1] = ff2 + (long)N_*FF_;
        dim3 gr(FF_ / 128, N_ / 128, 2);
        mma_gemm<2,128,true,true><<<gr,256,SMEM_G128>>>(p, D_, D_, D_, FF_);
    }
    // --- FFN2 (z=2, BM=64) -> t2 fp32 ---
    {
        GP<2> p{};
        p.A[0] = ff2;                p.B[0] = w2ih; p.bias[0] = b2i; p.Cf[0] = t2;
        p.A[1] = ff2 + (long)N_*FF_; p.B[1] = w2dh; p.bias[1] = b2d; p.Cf[1] = t2 + (long)N_*D_;
        dim3 gr(D_ / 128, N_ / 64, 2);
        mma_gemm<2,64,false,false><<<gr,256,SMEM_G64>>>(p, FF_, FF_, FF_, D_);
    }
    // --- LN2 -> out ---
    add_ln2_kernel<<<2*N_,128>>>(x2, x2 + (long)N_*D_, t2,
        lni + 2*D_, lni + 3*D_, lnd + 2*D_, lnd + 3*D_, out, nullptr);
}

// round 14
// speedup vs baseline: 1.0414x; 1.0092x over previous
#include <cuda_runtime.h>
#include <cuda_fp16.h>
#include <math.h>
#include <stdint.h>

// Problem constants
#define S_   1024
#define B_   8
#define D_   512
#define H_   8
#define HD_  64
#define FF_  2048
#define N_   (S_ * B_)      // 8192 tokens
#define NH_  (B_ * H_)      // 64 (batch*heads)
#define DD_  (D_ * D_)

// ===========================================================================
// PTX helpers — baseline-PTX only (compute_103 virtual arch: NO tcgen05)
// ===========================================================================
__device__ __forceinline__ uint32_t smem_u32(const void* p) {
    uint32_t a;
    asm("{ .reg .u64 t; cvta.to.shared.u64 t, %1; cvt.u32.u64 %0, t; }" : "=r"(a) : "l"(p));
    return a;
}

__device__ __forceinline__ void cpasync16(uint32_t s, const void* g) {
    asm volatile("cp.async.cg.shared.global [%0], [%1], 16;" :: "r"(s), "l"(g));
}
#define CP_COMMIT()  asm volatile("cp.async.commit_group;" ::: "memory")
#define CP_WAIT0()   asm volatile("cp.async.wait_group 0;" ::: "memory")
#define CP_WAIT1()   asm volatile("cp.async.wait_group 1;" ::: "memory")
#define CP_WAIT2()   asm volatile("cp.async.wait_group 2;" ::: "memory")

__device__ __forceinline__ void ldsm4(uint32_t r[4], uint32_t addr) {
    asm volatile("ldmatrix.sync.aligned.m8n8.x4.shared.b16 {%0,%1,%2,%3}, [%4];"
        : "=r"(r[0]), "=r"(r[1]), "=r"(r[2]), "=r"(r[3]) : "r"(addr));
}

__device__ __forceinline__ void ldsm4t(uint32_t r[4], uint32_t addr) {
    asm volatile("ldmatrix.sync.aligned.m8n8.x4.trans.shared.b16 {%0,%1,%2,%3}, [%4];"
        : "=r"(r[0]), "=r"(r[1]), "=r"(r[2]), "=r"(r[3]) : "r"(addr));
}

__device__ __forceinline__ void mma16816(float acc[4], const uint32_t a[4], const uint32_t b[2]) {
    asm volatile(
        "mma.sync.aligned.m16n8k16.row.col.f32.f16.f16.f32 "
        "{%0,%1,%2,%3}, {%4,%5,%6,%7}, {%8,%9}, {%0,%1,%2,%3};"
        : "+f"(acc[0]), "+f"(acc[1]), "+f"(acc[2]), "+f"(acc[3])
        : "r"(a[0]), "r"(a[1]), "r"(a[2]), "r"(a[3]), "r"(b[0]), "r"(b[1]));
}

// ===========================================================================
// Scratch (static device memory)
// ===========================================================================
__device__ __half g_wih[4*DD_], g_wdh[4*DD_];
__device__ __half g_w1ih[FF_*D_], g_w2ih[D_*FF_];
__device__ __half g_w1dh[FF_*D_], g_w2dh[D_*FF_];
__device__ __half g_qkinh[N_*D_];
__device__ __half g_srch[N_*D_], g_srcdh[N_*D_];
__device__ __half g_qh[N_*D_],  g_qdh[N_*D_];
__device__ __half g_kh[N_*D_],  g_kdh[N_*D_];
__device__ __half g_vh[N_*D_],  g_vdh[N_*D_];
__device__ __half g_oih[N_*D_], g_odh[N_*D_];
__device__ __half g_t2h[2*N_*D_];    // fp16 GEMM outputs (pre-LN y)
__device__ __half g_x2h[2*N_*D_];    // fp16 LN1 outputs (FFN1 input + LN2 residual)
__device__ __half g_ff2[2*N_*FF_];

// ===========================================================================
// Z-batched mma.sync GEMM (validated R10 config)
// ===========================================================================
template<int NZ>
struct GP {
    const __half* A[NZ];
    const __half* B[NZ];
    const float*  bias[NZ];
    float*        Cf[NZ];
    __half*       Ch[NZ];
};

template<int NZ, int BM_, bool RELU, bool HALF_OUT>
__global__ __launch_bounds__(256) void mma_gemm(
    GP<NZ> p, int K, int lda, int ldb, int ldc)
{
    constexpr int BN = 128;
    constexpr int WM = BM_ / 2;
    constexpr int MT = WM / 16;
    constexpr int RS = 80;
    constexpr int SA = BM_ * RS;
    constexpr int STAGE = SA + BN * RS;

    extern __shared__ char sm[];
    const uint32_t smb = smem_u32(sm);

    const int t = threadIdx.x;
    const int lane = t & 31, wid = t >> 5;
    const int wm = wid >> 2, wn = wid & 3;
    const int m0 = blockIdx.y * BM_, n0 = blockIdx.x * BN;
    const int z = blockIdx.z;

    const __half* __restrict__ Ah   = p.A[z];
    const __half* __restrict__ Bh   = p.B[z];
    const float*  __restrict__ bias = p.bias[z];
    float*  Cf = p.Cf[z];
    __half* Ch = p.Ch[z];

    const int NC = K >> 5;

    auto load_stage = [&](int chunk, int stage) {
        const long ka = (long)chunk * 32;
        const uint32_t sbase = smb + stage * STAGE;
        #pragma unroll
        for (int idx = t; idx < BM_ * 4; idx += 256) {
            const int row = idx >> 2, c = idx & 3;
            cpasync16(sbase + row * RS + c * 16,
                      Ah + (long)(m0 + row) * lda + ka + c * 8);
        }
        #pragma unroll
        for (int idx = t; idx < BN * 4; idx += 256) {
            const int row = idx >> 2, c = idx & 3;
            cpasync16(sbase + SA + row * RS + c * 16,
                      Bh + (long)(n0 + row) * ldb + ka + c * 8);
        }
        CP_COMMIT();
    };

    float acc[MT][4][4] = {};

    load_stage(0, 0);
    if (NC > 1) load_stage(1, 1);

    for (int c = 0; c < NC; c++) {
        if (c + 2 < NC) { load_stage(c + 2, (c + 2) % 3); CP_WAIT2(); }
        else if (c + 1 < NC) CP_WAIT1();
        else CP_WAIT0();
        __syncthreads();

        const uint32_t sbase = smb + (c % 3) * STAGE;

        #pragma unroll
        for (int ks = 0; ks < 2; ks++) {
            const uint32_t koff = ks * 32 + (lane >> 4) * 16;

            uint32_t ah[MT][4];
            #pragma unroll
            for (int mi = 0; mi < MT; mi++) {
                const int row = wm * WM + mi * 16 + (lane & 15);
                ldsm4(ah[mi], sbase + row * RS + koff);
            }

            uint32_t bh[4][2];
            #pragma unroll
            for (int nj = 0; nj < 2; nj++) {
                const int row = wn * 32 + nj * 16 + (lane & 15);
                uint32_t r[4];
                ldsm4(r, sbase + SA + row * RS + koff);
                bh[2*nj][0]   = r[0]; bh[2*nj][1]   = r[2];
                bh[2*nj+1][0] = r[1]; bh[2*nj+1][1] = r[3];
            }

            #pragma unroll
            for (int mi = 0; mi < MT; mi++)
                #pragma unroll
                for (int nt = 0; nt < 4; nt++)
                    mma16816(acc[mi][nt], ah[mi], bh[nt]);
        }
        __syncthreads();
    }

    const int gid = lane >> 2, tig = lane & 3;
    #pragma unroll
    for (int mi = 0; mi < MT; mi++) {
        #pragma unroll
        for (int nt = 0; nt < 4; nt++) {
            const int col = n0 + wn * 32 + nt * 8 + tig * 2;
            float2 bb = *(const float2*)(bias + col);
            #pragma unroll
            for (int h = 0; h < 2; h++) {
                const int row = m0 + wm * WM + mi * 16 + gid + h * 8;
                float vx = acc[mi][nt][2*h+0] + bb.x;
                float vy = acc[mi][nt][2*h+1] + bb.y;
                if (RELU) { vx = fmaxf(vx, 0.f); vy = fmaxf(vy, 0.f); }
                const long off = (long)row * ldc + col;
                if (!HALF_OUT) {
                    *(float2*)(Cf + off) = make_float2(vx, vy);
                } else {
                    __half2 hh;
                    hh.x = __float2half_rn(vx);
                    hh.y = __float2half_rn(vy);
                    *(__half2*)(Ch + off) = hh;
                }
            }
        }
    }
}

// ===========================================================================
// Fused dual-stream attention (flash-style), R13 config (3-stage, Q-recycle)
// ===========================================================================
__global__ __launch_bounds__(256) void flash_kernel(
    const __half* __restrict__ Qi, const __half* __restrict__ Ki,
    const __half* __restrict__ Qd, const __half* __restrict__ Kd,
    const __half* __restrict__ Vi, const __half* __restrict__ Vd,
    __half* __restrict__ Oi, __half* __restrict__ Od)
{
    constexpr int RS2 = 144;
    constexpr int TK  = 64 * RS2;
    constexpr int STG = 4 * TK;

    extern __shared__ char sm[];
    const uint32_t smb = smem_u32(sm);

    const int t = threadIdx.x, lane = t & 31, wid = t >> 5;
    const int g = wid >> 2, w4 = wid & 3;
    const int z = blockIdx.y;
    const long base  = (long)z * 64;
    const int q0 = blockIdx.x * 64;
    const float scale = 0.125f;

    for (int idx = t; idx < 64 * 8; idx += 256) {
        const int row = idx >> 3, c = idx & 7;
        const long ga = base + (long)(q0 + row) * 4096 + c * 8;
        cpasync16(smb + 2 * STG +      row * RS2 + c * 16, Qi + ga);
        cpasync16(smb + 2 * STG + TK + row * RS2 + c * 16, Qd + ga);
    }
    CP_COMMIT();

    auto load_stage = [&](int kb, int st) {
        const uint32_t sb = smb + st * STG;
        for (int idx = t; idx < 64 * 8; idx += 256) {
            const int row = idx >> 3, c = idx & 7;
            const long ga = base + (long)(kb * 64 + row) * 4096 + c * 8;
            cpasync16(sb +         row * RS2 + c * 16, Ki + ga);
            cpasync16(sb +   TK +  row * RS2 + c * 16, Kd + ga);
            cpasync16(sb + 2*TK +  row * RS2 + c * 16, Vi + ga);
            cpasync16(sb + 3*TK +  row * RS2 + c * 16, Vd + ga);
        }
        CP_COMMIT();
    };

    load_stage(0, 0);
    load_stage(1, 1);
    CP_WAIT2();
    __syncthreads();

    uint32_t aq[4][4];
    {
        const uint32_t qsm = smb + 2 * STG + g * TK;
        const int row = w4 * 16 + (lane & 15);
        #pragma unroll
        for (int c = 0; c < 4; c++)
            ldsm4(aq[c], qsm + row * RS2 + c * 32 + (lane >> 4) * 16);
    }
    __syncthreads();

    float uv[8][4] = {};
    float ud[8][4] = {};
    float ls0 = 0.f, ls1 = 0.f;

    for (int kb = 0; kb < 16; kb++) {
        if (kb + 2 < 16) { load_stage(kb + 2, (kb + 2) % 3); CP_WAIT2(); }
        else if (kb + 1 < 16) CP_WAIT1();
        else CP_WAIT0();
        __syncthreads();

        const uint32_t sb  = smb + (kb % 3) * STG;
        const uint32_t ksm = sb + g * TK;
        const uint32_t vi  = sb + 2 * TK;
        const uint32_t vd  = sb + 3 * TK;
        const int lrow = lane & 15;
        const uint32_t lk = (lane >> 4) * 16;

        float s[8][4] = {};
        #pragma unroll
        for (int c = 0; c < 4; c++) {
            uint32_t bk[8][2];
            #pragma unroll
            for (int nj = 0; nj < 4; nj++) {
                uint32_t r[4];
                ldsm4(r, ksm + (nj * 16 + lrow) * RS2 + c * 32 + lk);
                bk[2*nj][0]   = r[0]; bk[2*nj][1]   = r[2];
                bk[2*nj+1][0] = r[1]; bk[2*nj+1][1] = r[3];
            }
            #pragma unroll
            for (int nt = 0; nt < 8; nt++) mma16816(s[nt], aq[c], bk[nt]);
        }

        uint32_t pa[4][4];
        #pragma unroll
        for (int nt = 0; nt < 8; nt++) {
            float e0 = __expf(s[nt][0] * scale);
            float e1 = __expf(s[nt][1] * scale);
            float e2 = __expf(s[nt][2] * scale);
            float e3 = __expf(s[nt][3] * scale);
            ls0 += e0 + e1;
            ls1 += e2 + e3;
            __half2 p01 = __floats2half2_rn(e0, e1);
            __half2 p23 = __floats2half2_rn(e2, e3);
            pa[nt >> 1][(nt & 1) * 2 + 0] = *(uint32_t*)&p01;
            pa[nt >> 1][(nt & 1) * 2 + 1] = *(uint32_t*)&p23;
        }

        #pragma unroll
        for (int c = 0; c < 4; c++) {
            uint32_t bv[8][2];
            #pragma unroll
            for (int ng = 0; ng < 4; ng++) {
                uint32_t r[4];
                ldsm4t(r, vi + (c * 16 + lrow) * RS2 + ng * 32 + lk);
                bv[2*ng][0]   = r[0]; bv[2*ng][1]   = r[1];
                bv[2*ng+1][0] = r[2]; bv[2*ng+1][1] = r[3];
            }
            #pragma unroll
            for (int nt = 0; nt < 8; nt++) mma16816(uv[nt], pa[c], bv[nt]);
            #pragma unroll
            for (int ng = 0; ng < 4; ng++) {
                uint32_t r[4];
                ldsm4t(r, vd + (c * 16 + lrow) * RS2 + ng * 32 + lk);
                bv[2*ng][0]   = r[0]; bv[2*ng][1]   = r[1];
                bv[2*ng+1][0] = r[2]; bv[2*ng+1][1] = r[3];
            }
            #pragma unroll
            for (int nt = 0; nt < 8; nt++) mma16816(ud[nt], pa[c], bv[nt]);
        }
        __syncthreads();
    }

    ls0 += __shfl_xor_sync(0xffffffffu, ls0, 1);
    ls0 += __shfl_xor_sync(0xffffffffu, ls0, 2);
    ls1 += __shfl_xor_sync(0xffffffffu, ls1, 1);
    ls1 += __shfl_xor_sync(0xffffffffu, ls1, 2);
    const float inv0 = 0.5f / ls0;
    const float inv1 = 0.5f / ls1;

    __syncthreads();
    float* so_i = (float*)sm;
    float* so_d = (float*)(sm + 64 * 68 * 4);
    const int gid = lane >> 2, tig = lane & 3;
    const int r0 = w4 * 16 + gid;

    if (g == 0) {
        #pragma unroll
        for (int nt = 0; nt < 8; nt++) {
            const int col = nt * 8 + tig * 2;
            so_i[ r0      * 68 + col]     = uv[nt][0] * inv0;
            so_i[ r0      * 68 + col + 1] = uv[nt][1] * inv0;
            so_i[(r0 + 8) * 68 + col]     = uv[nt][2] * inv1;
            so_i[(r0 + 8) * 68 + col + 1] = uv[nt][3] * inv1;
            so_d[ r0      * 68 + col]     = ud[nt][0] * inv0;
            so_d[ r0      * 68 + col + 1] = ud[nt][1] * inv0;
            so_d[(r0 + 8) * 68 + col]     = ud[nt][2] * inv1;
            so_d[(r0 + 8) * 68 + col + 1] = ud[nt][3] * inv1;
        }
    }
    __syncthreads();
    if (g == 1) {
        #pragma unroll
        for (int nt = 0; nt < 8; nt++) {
            const int col = nt * 8 + tig * 2;
            const long oa0 = base + (long)(q0 + r0)     * 4096 + col;
            const long oa1 = base + (long)(q0 + r0 + 8) * 4096 + col;
            __half2 h;
            h.x = __float2half_rn(so_i[ r0      * 68 + col]     + uv[nt][0] * inv0);
            h.y = __float2half_rn(so_i[ r0      * 68 + col + 1] + uv[nt][1] * inv0);
            *(__half2*)(Oi + oa0) = h;
            h.x = __float2half_rn(so_i[(r0 + 8) * 68 + col]     + uv[nt][2] * inv1);
            h.y = __float2half_rn(so_i[(r0 + 8) * 68 + col + 1] + uv[nt][3] * inv1);
            *(__half2*)(Oi + oa1) = h;
            h.x = __float2half_rn(so_d[ r0      * 68 + col]     + ud[nt][0] * inv0);
            h.y = __float2half_rn(so_d[ r0      * 68 + col + 1] + ud[nt][1] * inv0);
            *(__half2*)(Od + oa0) = h;
            h.x = __float2half_rn(so_d[(r0 + 8) * 68 + col]     + ud[nt][2] * inv1);
            h.y = __float2half_rn(so_d[(r0 + 8) * 68 + col + 1] + ud[nt][3] * inv1);
            *(__half2*)(Od + oa1) = h;
        }
    }
}

// ===========================================================================
// Elementwise kernels
// ===========================================================================
// 18 segments of 1M elems; each thread does 4 independent float4 loads (MLP=4).
// Block covers 4096 elements; 256 blocks per segment.
struct CV18 { const float* a[18]; const float* b[18]; __half* dst[18]; };
__global__ __launch_bounds__(256) void conv18_kernel(CV18 w)
{
    const int seg = blockIdx.x >> 8;              // /256
    const long blkbase = (long)(blockIdx.x & 255) * 4096 + threadIdx.x * 4;
    const float* xa = w.a[seg];
    const float* xb = w.b[seg];
    __half* h = w.dst[seg];

    float4 v[4];
    #pragma unroll
    for (int j = 0; j < 4; j++) v[j] = *(const float4*)(xa + blkbase + j * 1024);
    if (xb) {
        #pragma unroll
        for (int j = 0; j < 4; j++) {
            float4 u = *(const float4*)(xb + blkbase + j * 1024);
            v[j].x += u.x; v[j].y += u.y; v[j].z += u.z; v[j].w += u.w;
        }
    }
    #pragma unroll
    for (int j = 0; j < 4; j++) {
        __half2 h01, h23;
        h01.x = __float2half_rn(v[j].x); h01.y = __float2half_rn(v[j].y);
        h23.x = __float2half_rn(v[j].z); h23.y = __float2half_rn(v[j].w);
        *(__half2*)(h + blkbase + j * 1024)     = h01;
        *(__half2*)(h + blkbase + j * 1024 + 2) = h23;
    }
}

// Batched residual + LayerNorm over [2N] rows; y is fp16.
// RES_HALF: residual tensors are fp16. OUT_FLOAT: write fp32 outf, else fp16 outh.
template<bool RES_HALF, bool OUT_FLOAT>
__global__ __launch_bounds__(128) void add_lnT_kernel(
    const void* __restrict__ xv0, const void* __restrict__ xv1,
    const __half* __restrict__ y,
    const float* __restrict__ ga0, const float* __restrict__ be0,
    const float* __restrict__ ga1, const float* __restrict__ be1,
    float* __restrict__ outf, __half* __restrict__ outh)
{
    const long n = blockIdx.x;
    const int zz = n >= N_;
    const long local = zz ? n - N_ : n;
    const int t = threadIdx.x;

    const float* gamma = zz ? ga1 : ga0;
    const float* beta  = zz ? be1 : be0;

    float x0f, x1f, x2f, x3f;
    if (RES_HALF) {
        const __half* x = ((const __half*)(zz ? xv1 : xv0)) + local * D_ + t * 4;
        __half2 a01 = *(const __half2*)x;
        __half2 a23 = *(const __half2*)(x + 2);
        x0f = __half2float(a01.x); x1f = __half2float(a01.y);
        x2f = __half2float(a23.x); x3f = __half2float(a23.y);
    } else {
        float4 a = ((const float4*)((const float*)(zz ? xv1 : xv0) + local * D_))[t];
        x0f = a.x; x1f = a.y; x2f = a.z; x3f = a.w;
    }

    const __half* yp = y + n * D_ + t * 4;
    __half2 y01 = *(const __half2*)yp;
    __half2 y23 = *(const __half2*)(yp + 2);

    float v0 = x0f + __half2float(y01.x);
    float v1 = x1f + __half2float(y01.y);
    float v2 = x2f + __half2float(y23.x);
    float v3 = x3f + __half2float(y23.y);

    float s  = v0 + v1 + v2 + v3;
    float sq = v0 * v0 + v1 * v1 + v2 * v2 + v3 * v3;

    __shared__ float sh[2][4];
    #pragma unroll
    for (int o = 16; o > 0; o >>= 1) {
        s  += __shfl_xor_sync(0xffffffffu, s,  o);
        sq += __shfl_xor_sync(0xffffffffu, sq, o);
    }
    if ((t & 31) == 0) { sh[0][t >> 5] = s; sh[1][t >> 5] = sq; }
    __syncthreads();
    s  = sh[0][0] + sh[0][1] + sh[0][2] + sh[0][3];
    sq = sh[1][0] + sh[1][1] + sh[1][2] + sh[1][3];

    const float mean = s * (1.0f / D_);
    const float var  = sq * (1.0f / D_) - mean * mean;
    const float inv  = rsqrtf(var + 1e-5f);

    float4 gg = ((const float4*)gamma)[t];
    float4 bb = ((const float4*)beta)[t];
    float o0 = (v0 - mean) * inv * gg.x + bb.x;
    float o1 = (v1 - mean) * inv * gg.y + bb.y;
    float o2 = (v2 - mean) * inv * gg.z + bb.z;
    float o3 = (v3 - mean) * inv * gg.w + bb.w;

    if (OUT_FLOAT) {
        float4 o4 = make_float4(o0, o1, o2, o3);
        ((float4*)(outf + n * D_))[t] = o4;
    } else {
        long i = n * D_ + t * 4;
        __half2 h01, h23;
        h01.x = __float2half_rn(o0); h01.y = __float2half_rn(o1);
        h23.x = __float2half_rn(o2); h23.y = __float2half_rn(o3);
        *(__half2*)(outh + i)     = h01;
        *(__half2*)(outh + i + 2) = h23;
    }
}

// ===========================================================================
// Launch
// ===========================================================================
#define SYM(p, s) do { void* _q; cudaGetSymbolAddress(&_q, s); p = (decltype(p))_q; } while (0)

extern "C" void kernel_launch(void* const* d_in, const int* in_sizes, int n_in,
                              void* d_out, int out_size)
{
    const float* src  = (const float*)d_in[0];
    const float* srcd = (const float*)d_in[1];
    const float* pos  = (const float*)d_in[2];
    const float* wi   = (const float*)d_in[3];
    const float* bi   = (const float*)d_in[4];
    const float* wd   = (const float*)d_in[5];
    const float* bd   = (const float*)d_in[6];
    const float* w1i  = (const float*)d_in[7];
    const float* b1i  = (const float*)d_in[8];
    const float* w2i  = (const float*)d_in[9];
    const float* b2i  = (const float*)d_in[10];
    const float* w1d  = (const float*)d_in[11];
    const float* b1d  = (const float*)d_in[12];
    const float* w2d  = (const float*)d_in[13];
    const float* b2d  = (const float*)d_in[14];
    const float* lni  = (const float*)d_in[15];
    const float* lnd  = (const float*)d_in[16];
    float* out = (float*)d_out;

    __half *wih,*wdh,*w1ih,*w2ih,*w1dh,*w2dh;
    __half *qkinh,*srch,*srcdh;
    __half *qh,*qdh,*kh,*kdh,*vh,*vdh;
    __half *oih,*odh,*x2h,*ff2,*t2h;

    SYM(wih, g_wih);   SYM(wdh, g_wdh);
    SYM(w1ih, g_w1ih); SYM(w2ih, g_w2ih);
    SYM(w1dh, g_w1dh); SYM(w2dh, g_w2dh);
    SYM(qkinh, g_qkinh);
    SYM(srch, g_srch); SYM(srcdh, g_srcdh);
    SYM(qh, g_qh); SYM(qdh, g_qdh);
    SYM(kh, g_kh); SYM(kdh, g_kdh);
    SYM(vh, g_vh); SYM(vdh, g_vdh);
    SYM(oih, g_oih); SYM(odh, g_odh);
    SYM(t2h, g_t2h); SYM(x2h, g_x2h);
    SYM(ff2, g_ff2);

    constexpr int SMEM_G128 = 3 * (128 * 80 + 128 * 80);           // 61440
    constexpr int SMEM_G64  = 3 * ( 64 * 80 + 128 * 80);           // 46080
    constexpr int SMEM_FLASH = 3 * (4 * 64 * 144);                 // 110592
    cudaFuncSetAttribute((const void*)&mma_gemm<6,128,false,true>,
                         cudaFuncAttributeMaxDynamicSharedMemorySize, SMEM_G128);
    cudaFuncSetAttribute((const void*)&mma_gemm<2,128,true,true>,
                         cudaFuncAttributeMaxDynamicSharedMemorySize, SMEM_G128);
    cudaFuncSetAttribute((const void*)&mma_gemm<2,64,false,true>,
                         cudaFuncAttributeMaxDynamicSharedMemorySize, SMEM_G64);
    cudaFuncSetAttribute((const void*)&flash_kernel,
                         cudaFuncAttributeMaxDynamicSharedMemorySize, SMEM_FLASH);

    // --- ALL conversions (weights + activations) in ONE launch, MLP=4 ---
    {
        CV18 w{};
        w.a[0] = wi;   w.dst[0] = wih;
        w.a[1] = wd;   w.dst[1] = wdh;
        w.a[2] = w1i;  w.dst[2] = w1ih;
        w.a[3] = w2i;  w.dst[3] = w2ih;
        w.a[4] = w1d;  w.dst[4] = w1dh;
        w.a[5] = w2d;  w.dst[5] = w2dh;
        #pragma unroll
        for (int s = 0; s < 4; s++) {
            w.a[6 + s]  = src  + ((long)s << 20); w.b[6 + s] = pos + ((long)s << 20);
            w.dst[6 + s] = qkinh + ((long)s << 20);
            w.a[10 + s] = src  + ((long)s << 20); w.dst[10 + s] = srch  + ((long)s << 20);
            w.a[14 + s] = srcd + ((long)s << 20); w.dst[14 + s] = srcdh + ((long)s << 20);
        }
        conv18_kernel<<<18 * 256, 256>>>(w);
    }

    // --- all six projections in ONE z=6 launch ---
    {
        GP<6> p{};
        p.A[0] = qkinh; p.B[0] = wih;          p.bias[0] = bi;          p.Ch[0] = qh;
        p.A[1] = qkinh; p.B[1] = wih + DD_;    p.bias[1] = bi + D_;     p.Ch[1] = kh;
        p.A[2] = srch;  p.B[2] = wih + 2*DD_;  p.bias[2] = bi + 2*D_;   p.Ch[2] = vh;
        p.A[3] = srcdh; p.B[3] = wdh;          p.bias[3] = bd;          p.Ch[3] = qdh;
        p.A[4] = srcdh; p.B[4] = wdh + DD_;    p.bias[4] = bd + D_;     p.Ch[4] = kdh;
        p.A[5] = srcdh; p.B[5] = wdh + 2*DD_;  p.bias[5] = bd + 2*D_;   p.Ch[5] = vdh;
        dim3 gProj(D_ / 128, N_ / 128, 6);
        mma_gemm<6,128,false,true><<<gProj,256,SMEM_G128>>>(p, D_, D_, D_, D_);
    }

    // --- fused attention ---
    dim3 gFl(S_ / 64, NH_, 1);
    flash_kernel<<<gFl, 256, SMEM_FLASH>>>(qh, kh, qdh, kdh, vh, vdh, oih, odh);

    // --- out-proj (z=2, BM=64) -> t2h fp16 ---
    {
        GP<2> p{};
        p.A[0] = oih; p.B[0] = wih + 3*DD_; p.bias[0] = bi + 3*D_; p.Ch[0] = t2h;
        p.A[1] = odh; p.B[1] = wdh + 3*DD_; p.bias[1] = bd + 3*D_; p.Ch[1] = t2h + (long)N_*D_;
        dim3 gr(D_ / 128, N_ / 64, 2);
        mma_gemm<2,64,false,true><<<gr,256,SMEM_G64>>>(p, D_, D_, D_, D_);
    }
    // --- LN1: fp32 residual (src/srcd) + fp16 y -> fp16 x2h only ---
    add_lnT_kernel<false,false><<<2*N_,128>>>(src, srcd, t2h,
        lni, lni + D_, lnd, lnd + D_, nullptr, x2h);
    // --- FFN1 (+ReLU) (z=2) ---
    {
        GP<2> p{};
        p.A[0] = x2h;               p.B[0] = w1ih; p.bias[0] = b1i; p.Ch[0] = ff2;
        p.A[1] = x2h + (long)N_*D_; p.B[1] = w1dh; p.bias[1] = b1d; p.Ch[1] = ff2 + (long)N_*FF_;
        dim3 gr(FF_ / 128, N_ / 128, 2);
        mma_gemm<2,128,true,true><<<gr,256,SMEM_G128>>>(p, D_, D_, D_, FF_);
    }
    // --- FFN2 (z=2, BM=64) -> t2h fp16 ---
    {
        GP<2> p{};
        p.A[0] = ff2;                p.B[0] = w2ih; p.bias[0] = b2i; p.Ch[0] = t2h;
        p.A[1] = ff2 + (long)N_*FF_; p.B[1] = w2dh; p.bias[1] = b2d; p.Ch[1] = t2h + (long)N_*D_;
        dim3 gr(D_ / 128, N_ / 64, 2);
        mma_gemm<2,64,false,true><<<gr,256,SMEM_G64>>>(p, FF_, FF_, FF_, D_);
    }
    // --- LN2: fp16 residual (x2h) + fp16 y -> fp32 out ---
    add_lnT_kernel<true,true><<<2*N_,128>>>(x2h, x2h + (long)N_*D_, t2h,
        lni + 2*D_, lni + 3*D_, lnd + 2*D_, lnd + 3*D_, out, nullptr);
}